// round 14
// baseline (speedup 1.0000x reference)
#include <cuda_runtime.h>
#include <cstdint>

#define BATCH 32
#define L_ 512
#define T_ 64
#define NCHUNK 32
#define CSTEPS 16
#define EPITCH 66

// rank-1 chunk factors: a_c (forward), b_c (backward), backward exponents
__device__ float g_a[BATCH][NCHUNK][T_];
__device__ float g_bv[BATCH][NCHUNK][T_];
__device__ int   g_eb[BATCH][NCHUNK];
__device__ int   g_cnt[BATCH];          // zero-init; reset to 0 by combiner

typedef unsigned long long u64;
__device__ __forceinline__ u64 pk(float lo, float hi) {
    u64 r; asm("mov.b64 %0,{%1,%2};" : "=l"(r) : "f"(lo), "f"(hi)); return r;
}
__device__ __forceinline__ void upk(u64 v, float& lo, float& hi) {
    asm("mov.b64 {%0,%1},%2;" : "=f"(lo), "=f"(hi) : "l"(v));
}
#define FMA2(acc, a, b) asm("fma.rn.f32x2 %0,%1,%2,%0;" : "+l"(acc) : "l"(a), "l"(b))
#define ADD2(d, a, b)   asm("add.rn.f32x2 %0,%1,%2;"    : "=l"(d)   : "l"(a), "l"(b))

// ===========================================================================
// Fused kernel: CTA = (batch b, chunk c), 16 steps per chunk.
//  Warp 0: a_c = P_c 1 (ascending t).  Warp 1: b_c = P_c^T 1 (descending).
//  Exact 2^e renorm per step (exponent carried in a register, shfl-broadcast).
//  Masked / out-of-range steps skipped (exact identity).
//  Phase 2: last-arriver (32nd) CTA per batch combines inline:
//    logZ = sum_c log(b_c . a_{c-1}) - sum_{c<31} log(1^T a_c) + ln2*sum EB
// ===========================================================================
__global__ void __launch_bounds__(64, 7) crf_rank1_fused(
    const float* __restrict__ logits,
    const int* __restrict__ mask,
    const float* __restrict__ trans,
    float* __restrict__ out)
{
    __shared__ __align__(16) float Ex[T_ * EPITCH];  // Ex[i][j] = exp(trans[i][j])
    __shared__ __align__(16) float ubuf[2][T_];
    __shared__ __align__(16) float wbuf[2][T_];
    __shared__ int msk_s[CSTEPS];
    __shared__ int old_s;
    __shared__ float dots_s[NCHUNK], gams_s[NCHUNK];
    __shared__ int eb_s[NCHUNK];

    const int b = blockIdx.x >> 5, c = blockIdx.x & 31;
    const int tid = threadIdx.x, w = tid >> 5, l = tid & 31;
    const int t0 = 1 + CSTEPS * c;

    #pragma unroll 4
    for (int r = 0; r < T_; r++)
        Ex[r * EPITCH + tid] = __expf(trans[r * T_ + tid]);
    if (tid < CSTEPS) {
        int t = t0 + tid;
        msk_s[tid] = (t < L_) ? mask[(size_t)b * L_ + t] : 0;
    }
    ubuf[0][tid] = 1.0f;
    __syncthreads();

    const float* lg = logits + ((size_t)b * L_) * T_ + 2 * l;

    if (w == 0) {
        // -------- forward chain: u'_j = g_j * sum_i u_i E[i][j] --------
        u64 F0[32], F1[32];   // columns 2l, 2l+1, packed over i-pairs
        #pragma unroll
        for (int i2 = 0; i2 < 32; i2++) {
            F0[i2] = pk(Ex[(2 * i2) * EPITCH + 2 * l],
                        Ex[(2 * i2 + 1) * EPITCH + 2 * l]);
            F1[i2] = pk(Ex[(2 * i2) * EPITCH + 2 * l + 1],
                        Ex[(2 * i2 + 1) * EPITCH + 2 * l + 1]);
        }
        float2 gA = *(const float2*)(lg + (size_t)t0 * T_);        // t0 <= 481
        float2 gB = *(const float2*)(lg + (size_t)(t0 + 1) * T_);  // <= 482
        float u0reg = 1.0f;   // current u[0], register-carried
        int p = 0;
        #pragma unroll 1
        for (int i = 0; i < CSTEPS; i++) {
            float2 gp = gA; gA = gB;
            int t2 = t0 + i + 2;
            if (t2 < L_) gB = *(const float2*)(lg + (size_t)t2 * T_);
            if (msk_s[i]) {
                int e = ((__float_as_int(u0reg) >> 23) & 255) - 127;
                float sc = __int_as_float((127 - e) << 23);
                float gx = __expf(gp.x) * sc, gy = __expf(gp.y) * sc;
                const float4* u4 = (const float4*)ubuf[p];
                u64 a00 = 0, a01 = 0, a10 = 0, a11 = 0;
                #pragma unroll
                for (int k4 = 0; k4 < 16; k4++) {
                    float4 uu = u4[k4];
                    u64 p0 = pk(uu.x, uu.y), p1 = pk(uu.z, uu.w);
                    FMA2(a00, F0[2 * k4], p0); FMA2(a01, F0[2 * k4 + 1], p1);
                    FMA2(a10, F1[2 * k4], p0); FMA2(a11, F1[2 * k4 + 1], p1);
                }
                u64 s0, s1; ADD2(s0, a00, a01); ADD2(s1, a10, a11);
                float x0, x1, y0, y1; upk(s0, x0, x1); upk(s1, y0, y1);
                float vx = (x0 + x1) * gx, vy = (y0 + y1) * gy;
                ((float2*)ubuf[p ^ 1])[l] = make_float2(vx, vy);
                u0reg = __shfl_sync(0xffffffffu, vx, 0);
                p ^= 1;
            }
            __syncwarp();
        }
        ((float2*)g_a[b][c])[l] = ((const float2*)ubuf[p])[l];
    } else {
        // -------- backward chain: b'_i = sum_j E[i][j] (g_j b_j) --------
        u64 B0[32], B1[32];   // rows 2l, 2l+1, packed over j-pairs
        #pragma unroll
        for (int j2 = 0; j2 < 32; j2++) {
            float2 r0 = *(const float2*)&Ex[(2 * l) * EPITCH + 2 * j2];
            float2 r1 = *(const float2*)&Ex[(2 * l + 1) * EPITCH + 2 * j2];
            B0[j2] = pk(r0.x, r0.y);
            B1[j2] = pk(r1.x, r1.y);
        }
        const int thi = t0 + CSTEPS - 1;
        float2 gA = (thi < L_) ? *(const float2*)(lg + (size_t)thi * T_)
                               : make_float2(0.0f, 0.0f);
        float2 gB = *(const float2*)(lg + (size_t)(thi - 1) * T_);
        float bx = 1.0f, by = 1.0f;
        int p = 0, keb = 0;
        #pragma unroll 1
        for (int i = CSTEPS - 1; i >= 0; i--) {
            float2 gp = gA; gA = gB;
            if (i >= 2) gB = *(const float2*)(lg + (size_t)(t0 + i - 2) * T_);
            if (msk_s[i]) {
                float b0 = __shfl_sync(0xffffffffu, bx, 0);
                int e = ((__float_as_int(b0) >> 23) & 255) - 127;
                float sc = __int_as_float((127 - e) << 23);
                keb += e;
                float wx = __expf(gp.x) * bx * sc;
                float wy = __expf(gp.y) * by * sc;
                ((float2*)wbuf[p])[l] = make_float2(wx, wy);
                __syncwarp();
                const float4* w4 = (const float4*)wbuf[p];
                u64 a00 = 0, a01 = 0, a10 = 0, a11 = 0;
                #pragma unroll
                for (int k4 = 0; k4 < 16; k4++) {
                    float4 ww = w4[k4];
                    u64 p0 = pk(ww.x, ww.y), p1 = pk(ww.z, ww.w);
                    FMA2(a00, B0[2 * k4], p0); FMA2(a01, B0[2 * k4 + 1], p1);
                    FMA2(a10, B1[2 * k4], p0); FMA2(a11, B1[2 * k4 + 1], p1);
                }
                u64 s0, s1; ADD2(s0, a00, a01); ADD2(s1, a10, a11);
                float x0, x1, y0, y1; upk(s0, x0, x1); upk(s1, y0, y1);
                bx = x0 + x1; by = y0 + y1;
                p ^= 1;
            }
            __syncwarp();
        }
        ((float2*)g_bv[b][c])[l] = make_float2(bx, by);
        if (l == 0) g_eb[b][c] = keb;
    }

    // ---------------- Phase 2: last-arriver combine ----------------
    __threadfence();
    __syncthreads();
    if (tid == 0) old_s = atomicAdd(&g_cnt[b], 1);
    __syncthreads();
    if (old_s != NCHUNK - 1) return;
    __threadfence();   // acquire side

    {
        const int cc = tid >> 1, q = tid & 1;   // chunk cc, half q (32 floats)
        float4 pv[8];
        if (cc == 0) {
            const float m0 = (mask[(size_t)b * L_] != 0) ? 1.0f : 0.0f;
            const float* lg0 = logits + (size_t)b * L_ * T_ + q * 32;
            #pragma unroll
            for (int x = 0; x < 8; x++)
                pv[x] = make_float4(__expf(lg0[4 * x] * m0),
                                    __expf(lg0[4 * x + 1] * m0),
                                    __expf(lg0[4 * x + 2] * m0),
                                    __expf(lg0[4 * x + 3] * m0));
        } else {
            const float4* ap = (const float4*)&g_a[b][cc - 1][q * 32];
            #pragma unroll
            for (int x = 0; x < 8; x++) pv[x] = ap[x];
        }
        const float4* bv4 = (const float4*)&g_bv[b][cc][q * 32];
        const float4* ac4 = (const float4*)&g_a[b][cc][q * 32];
        float dv = 0.0f, ga = 0.0f;
        #pragma unroll
        for (int x = 0; x < 8; x++) {
            float4 bb = bv4[x];
            dv += bb.x * pv[x].x + bb.y * pv[x].y + bb.z * pv[x].z + bb.w * pv[x].w;
            float4 aa = ac4[x];
            ga += aa.x + aa.y + aa.z + aa.w;
        }
        dv += __shfl_down_sync(0xffffffffu, dv, 1);
        ga += __shfl_down_sync(0xffffffffu, ga, 1);
        if (q == 0) { dots_s[cc] = dv; gams_s[cc] = ga; }
        if (tid < NCHUNK) eb_s[tid] = g_eb[b][tid];
        __syncthreads();

        if (tid == 0) {
            float s = 0.0f; int ebs = 0;
            #pragma unroll
            for (int k = 0; k < NCHUNK; k++) { s += __logf(dots_s[k]); ebs += eb_s[k]; }
            #pragma unroll
            for (int k = 0; k < NCHUNK - 1; k++) s -= __logf(gams_s[k]);
            out[b] = s + 0.6931471805599453f * (float)ebs;
            g_cnt[b] = 0;   // reset for next graph replay (deterministic)
        }
    }
}

extern "C" void kernel_launch(void* const* d_in, const int* in_sizes, int n_in,
                              void* d_out, int out_size) {
    const float* logits = (const float*)d_in[0];  // (32,512,64) f32
    const int* mask     = (const int*)d_in[1];    // (32,512) bool -> int32
    const float* trans  = (const float*)d_in[2];  // (64,64) f32
    float* out          = (float*)d_out;          // (32,) f32
    (void)in_sizes; (void)n_in; (void)out_size;
    crf_rank1_fused<<<BATCH * NCHUNK, 64>>>(logits, mask, trans, out);
}

// round 15
// speedup vs baseline: 1.5431x; 1.5431x over previous
#include <cuda_runtime.h>
#include <cstdint>

#define BATCH 32
#define L_ 512
#define T_ 64
#define NCHUNK 16
#define CSTEPS 32
#define EPITCH 66

// rank-1 chunk factors: a_c (forward), b_c (backward), backward exponents
__device__ float g_a[BATCH][NCHUNK][T_];
__device__ float g_bv[BATCH][NCHUNK][T_];
__device__ int   g_eb[BATCH][NCHUNK];
__device__ int   g_cnt[BATCH];          // zero-init; reset to 0 by combiner

typedef unsigned long long u64;
__device__ __forceinline__ u64 pk(float lo, float hi) {
    u64 r; asm("mov.b64 %0,{%1,%2};" : "=l"(r) : "f"(lo), "f"(hi)); return r;
}
__device__ __forceinline__ void upk(u64 v, float& lo, float& hi) {
    asm("mov.b64 {%0,%1},%2;" : "=f"(lo), "=f"(hi) : "l"(v));
}
#define FMA2(acc, a, b) asm("fma.rn.f32x2 %0,%1,%2,%0;" : "+l"(acc) : "l"(a), "l"(b))
#define ADD2(d, a, b)   asm("add.rn.f32x2 %0,%1,%2;"    : "=l"(d)   : "l"(a), "l"(b))

// ===========================================================================
// Fused kernel, output-split: CTA = (batch b, chunk c), 128 threads.
//  Warps 0,1: forward chain a_c = P_c 1.  Lane owns output COLUMN jcol
//    (w0: l, w1: 32+l), holds E[:,jcol] as 32 u64 regs; per step reads full
//    u from SMEM (broadcast LDS.128), 32 FMA2, scales by g*2^-e, STS.32.
//  Warps 2,3: backward chain b_c = P_c^T 1.  Lane owns output ROW jcol,
//    holds E[jcol,:] as 32 u64; per step: STS w = g*b*2^-e (pre-bar), then
//    reads full w, 32 FMA2.  Renorm exponent from SMEM word 0 (uniform
//    across warps); bwd exponent lags one step (exact bookkeeping in keb).
//  One __syncthreads per step (all 4 warps, divergent call sites - legal).
//  Phase 2: last-arriver CTA per batch combines inline:
//    logZ = sum_c log(b_c . a_{c-1}) - sum_{c<15} log(1^T a_c) + ln2*sum EB
// ===========================================================================
__global__ void __launch_bounds__(128, 4) crf_rank1_fused(
    const float* __restrict__ logits,
    const int* __restrict__ mask,
    const float* __restrict__ trans,
    float* __restrict__ out)
{
    __shared__ __align__(16) float Ex[T_ * EPITCH];  // Ex[i][j] = exp(trans[i][j])
    __shared__ __align__(16) float ubuf[2][T_];
    __shared__ __align__(16) float wbuf[2][T_];
    __shared__ int msk_s[CSTEPS];
    __shared__ int old_s;
    __shared__ float dots_s[NCHUNK], gams_s[NCHUNK];
    __shared__ int eb_s[NCHUNK];

    const int b = blockIdx.x >> 4, c = blockIdx.x & 15;
    const int tid = threadIdx.x, w = tid >> 5, l = tid & 31;
    const int jcol = (w & 1) * 32 + l;   // owned column (fwd) / row (bwd)
    const int t0 = 1 + CSTEPS * c;

    for (int i = tid; i < T_ * T_; i += 128)
        Ex[(i >> 6) * EPITCH + (i & 63)] = __expf(trans[i]);
    if (tid < CSTEPS) {
        int t = t0 + tid;
        msk_s[tid] = (t < L_) ? mask[(size_t)b * L_ + t] : 0;
    }
    if (tid < T_) ubuf[0][tid] = 1.0f;
    __syncthreads();

    const float* lgc = logits + (size_t)b * L_ * T_ + jcol;   // + t*T_

    if (w < 2) {
        // ---------------- forward: v_jcol = sum_i u_i E[i][jcol] ----------
        u64 F[32];
        #pragma unroll
        for (int i2 = 0; i2 < 32; i2++)
            F[i2] = pk(Ex[(2 * i2) * EPITCH + jcol],
                       Ex[(2 * i2 + 1) * EPITCH + jcol]);
        float gA_ = lgc[(size_t)t0 * T_];          // t0 <= 481
        float gB_ = lgc[(size_t)(t0 + 1) * T_];    // <= 482
        float ulast = 1.0f;
        int p = 0;
        #pragma unroll 1
        for (int i = 0; i < CSTEPS; i++) {
            float gp = gA_; gA_ = gB_;
            int t2 = t0 + i + 2;
            if (t2 < L_) gB_ = lgc[(size_t)t2 * T_];
            if (msk_s[i]) {
                const ulonglong2* u2 = (const ulonglong2*)ubuf[p];
                ulonglong2 q0 = u2[0];
                float u0lo, u0hi; upk(q0.x, u0lo, u0hi);
                int e = ((__float_as_int(u0lo) >> 23) & 255) - 127;
                float sc = __int_as_float((127 - e) << 23);
                u64 a0 = 0, a1 = 0, a2 = 0, a3 = 0;
                FMA2(a0, q0.x, F[0]); FMA2(a1, q0.y, F[1]);
                ulonglong2 q1 = u2[1];
                FMA2(a2, q1.x, F[2]); FMA2(a3, q1.y, F[3]);
                #pragma unroll
                for (int k = 2; k < 16; k += 2) {
                    ulonglong2 qa = u2[k];
                    FMA2(a0, qa.x, F[2 * k]);     FMA2(a1, qa.y, F[2 * k + 1]);
                    ulonglong2 qb = u2[k + 1];
                    FMA2(a2, qb.x, F[2 * k + 2]); FMA2(a3, qb.y, F[2 * k + 3]);
                }
                u64 s0, s1, s2; ADD2(s0, a0, a1); ADD2(s1, a2, a3); ADD2(s2, s0, s1);
                float vlo, vhi; upk(s2, vlo, vhi);
                ulast = (vlo + vhi) * __expf(gp) * sc;
                ubuf[p ^ 1][jcol] = ulast;
                p ^= 1;
            }
            __syncthreads();
        }
        g_a[b][c][jcol] = ulast;
    } else {
        // ---------------- backward: b'_jcol = sum_j E[jcol][j] w_j --------
        u64 Br[32];
        #pragma unroll
        for (int j2 = 0; j2 < 32; j2++)
            Br[j2] = *(const u64*)&Ex[jcol * EPITCH + 2 * j2];
        const int thi = t0 + CSTEPS - 1;
        float gA_ = (thi < L_) ? lgc[(size_t)thi * T_] : 0.0f;
        float gB_ = lgc[(size_t)(thi - 1) * T_];   // thi-1 in [31,511]
        float bl = 1.0f;
        int ecarry = 0, keb = 0, q = 0;
        #pragma unroll 1
        for (int i = CSTEPS - 1; i >= 0; i--) {
            float gp = gA_; gA_ = gB_;
            if (i >= 2) gB_ = lgc[(size_t)(t0 + i - 2) * T_];
            if (msk_s[i]) {
                float sc = __int_as_float((127 - ecarry) << 23);
                keb += ecarry;
                wbuf[q][jcol] = __expf(gp) * bl * sc;
            }
            __syncthreads();
            if (msk_s[i]) {
                const ulonglong2* w2 = (const ulonglong2*)wbuf[q];
                ulonglong2 q0 = w2[0];
                float w0lo, w0hi; upk(q0.x, w0lo, w0hi);
                ecarry = ((__float_as_int(w0lo) >> 23) & 255) - 127;
                u64 a0 = 0, a1 = 0, a2 = 0, a3 = 0;
                FMA2(a0, q0.x, Br[0]); FMA2(a1, q0.y, Br[1]);
                ulonglong2 q1 = w2[1];
                FMA2(a2, q1.x, Br[2]); FMA2(a3, q1.y, Br[3]);
                #pragma unroll
                for (int k = 2; k < 16; k += 2) {
                    ulonglong2 qa = w2[k];
                    FMA2(a0, qa.x, Br[2 * k]);     FMA2(a1, qa.y, Br[2 * k + 1]);
                    ulonglong2 qb = w2[k + 1];
                    FMA2(a2, qb.x, Br[2 * k + 2]); FMA2(a3, qb.y, Br[2 * k + 3]);
                }
                u64 s0, s1, s2; ADD2(s0, a0, a1); ADD2(s1, a2, a3); ADD2(s2, s0, s1);
                float vlo, vhi; upk(s2, vlo, vhi);
                bl = vlo + vhi;
                q ^= 1;
            }
        }
        g_bv[b][c][jcol] = bl;
        if (w == 2 && l == 0) g_eb[b][c] = keb;
    }

    // ---------------- Phase 2: last-arriver combine ----------------
    __threadfence();
    __syncthreads();
    if (tid == 0) old_s = atomicAdd(&g_cnt[b], 1);
    __syncthreads();
    if (old_s != NCHUNK - 1) return;
    __threadfence();   // acquire side

    {
        const int cc = tid >> 3, qq = tid & 7;   // chunk cc, 8 lanes x 8 floats
        float4 pv[2];
        if (cc == 0) {
            const float m0 = (mask[(size_t)b * L_] != 0) ? 1.0f : 0.0f;
            const float* lg0 = logits + (size_t)b * L_ * T_ + qq * 8;
            #pragma unroll
            for (int x = 0; x < 2; x++)
                pv[x] = make_float4(__expf(lg0[4 * x] * m0),
                                    __expf(lg0[4 * x + 1] * m0),
                                    __expf(lg0[4 * x + 2] * m0),
                                    __expf(lg0[4 * x + 3] * m0));
        } else {
            const float4* ap = (const float4*)&g_a[b][cc - 1][qq * 8];
            pv[0] = ap[0]; pv[1] = ap[1];
        }
        const float4* bv4 = (const float4*)&g_bv[b][cc][qq * 8];
        const float4* ac4 = (const float4*)&g_a[b][cc][qq * 8];
        float dv = 0.0f, ga = 0.0f;
        #pragma unroll
        for (int x = 0; x < 2; x++) {
            float4 bb = bv4[x];
            dv += bb.x * pv[x].x + bb.y * pv[x].y + bb.z * pv[x].z + bb.w * pv[x].w;
            float4 aa = ac4[x];
            ga += aa.x + aa.y + aa.z + aa.w;
        }
        dv += __shfl_down_sync(0xffffffffu, dv, 4);
        dv += __shfl_down_sync(0xffffffffu, dv, 2);
        dv += __shfl_down_sync(0xffffffffu, dv, 1);
        ga += __shfl_down_sync(0xffffffffu, ga, 4);
        ga += __shfl_down_sync(0xffffffffu, ga, 2);
        ga += __shfl_down_sync(0xffffffffu, ga, 1);
        if (qq == 0) { dots_s[cc] = dv; gams_s[cc] = ga; }
        if (tid < NCHUNK) eb_s[tid] = g_eb[b][tid];
        __syncthreads();

        if (tid == 0) {
            float s = 0.0f; int ebs = 0;
            #pragma unroll
            for (int k = 0; k < NCHUNK; k++) { s += __logf(dots_s[k]); ebs += eb_s[k]; }
            #pragma unroll
            for (int k = 0; k < NCHUNK - 1; k++) s -= __logf(gams_s[k]);
            out[b] = s + 0.6931471805599453f * (float)ebs;
            g_cnt[b] = 0;   // reset for next graph replay (deterministic)
        }
    }
}

extern "C" void kernel_launch(void* const* d_in, const int* in_sizes, int n_in,
                              void* d_out, int out_size) {
    const float* logits = (const float*)d_in[0];  // (32,512,64) f32
    const int* mask     = (const int*)d_in[1];    // (32,512) bool -> int32
    const float* trans  = (const float*)d_in[2];  // (64,64) f32
    float* out          = (float*)d_out;          // (32,) f32
    (void)in_sizes; (void)n_in; (void)out_size;
    crf_rank1_fused<<<BATCH * NCHUNK, 128>>>(logits, mask, trans, out);
}